// round 2
// baseline (speedup 1.0000x reference)
#include <cuda_runtime.h>
#include <cuda_bf16.h>

// LSTM_24936580121326 R2: packed f32x2 gate FMAs + tanh.approx activations
// + X pre-transpose for coalesced per-step loads.

#define T_STEPS 49
#define MAX_B   131072

__device__ float g_XT[(size_t)T_STEPS * MAX_B];  // transposed X scratch [T][B]

// ---------------- helpers ----------------
typedef unsigned long long u64;

__device__ __forceinline__ u64 pack2(float lo, float hi) {
    u64 r;
    asm("mov.b64 %0, {%1, %2};" : "=l"(r) : "f"(lo), "f"(hi));
    return r;
}
__device__ __forceinline__ void unpack2(u64 v, float& lo, float& hi) {
    asm("mov.b64 {%0, %1}, %2;" : "=f"(lo), "=f"(hi) : "l"(v));
}
__device__ __forceinline__ u64 fma2(u64 a, u64 b, u64 c) {
    u64 d;
    asm("fma.rn.f32x2 %0, %1, %2, %3;" : "=l"(d) : "l"(a), "l"(b), "l"(c));
    return d;
}
__device__ __forceinline__ float tanhf_hw(float x) {
    float y;
    asm("tanh.approx.f32 %0, %1;" : "=f"(y) : "f"(x));
    return y;
}
__device__ __forceinline__ float sig_hw(float x) {
    return fmaf(0.5f, tanhf_hw(0.5f * x), 0.5f);
}

// ---------------- transpose X: [B,49] -> [49,B] ----------------
__global__ void __launch_bounds__(256) transpose_x_kernel(
    const float* __restrict__ X, int Bn)
{
    __shared__ float tile[32][51];  // 51: conflict-free (19,32 coprime)
    int b0 = blockIdx.x * 32;
    // coalesced read: X[b0*49 + i]
    for (int i = threadIdx.x; i < 32 * T_STEPS; i += blockDim.x) {
        int bb = i / T_STEPS, tt = i % T_STEPS;
        tile[bb][tt] = X[(size_t)b0 * T_STEPS + i];
    }
    __syncthreads();
    // coalesced write: XT[tt*Bn + b0 + bb]
    for (int i = threadIdx.x; i < 32 * T_STEPS; i += blockDim.x) {
        int tt = i / 32, bb = i % 32;
        g_XT[(size_t)tt * Bn + b0 + bb] = tile[bb][tt];
    }
}

// ---------------- main fused LSTM ----------------
__global__ void __launch_bounds__(256, 2) lstm_fused_kernel(
    const float* __restrict__ W_ih0, const float* __restrict__ W_hh0,
    const float* __restrict__ b_ih0, const float* __restrict__ b_hh0,
    const float* __restrict__ W_ih1, const float* __restrict__ W_hh1,
    const float* __restrict__ b_ih1, const float* __restrict__ b_hh1,
    const float* __restrict__ W_lin, const float* __restrict__ b_lin,
    float* __restrict__ out, int Bn)
{
    // Pair-interleaved weights: pair p covers gates (2p, 2p+1).
    // s_pw0[p][j] = float2{ W_hh0[2p][j], W_hh0[2p+1][j] }, consumed as ulonglong2.
    __shared__ float2 s_pw0[16][8];   // layer1 W_hh
    __shared__ float2 s_pu1[16][8];   // layer2 W_ih
    __shared__ float2 s_pv1[16][8];   // layer2 W_hh
    __shared__ float  s_pb0[32];      // pair-contiguous == natural order
    __shared__ float  s_pb1[32];
    __shared__ float  s_pwih0[32];
    __shared__ float  s_wlin[8];
    __shared__ float  s_blin;

    int tid = threadIdx.x;
    if (tid < 32) {
        s_pb0[tid]   = b_ih0[tid] + b_hh0[tid];
        s_pb1[tid]   = b_ih1[tid] + b_hh1[tid];
        s_pwih0[tid] = W_ih0[tid];
    }
    if (tid < 256) {
        int k = tid >> 3, j = tid & 7;   // gate k, column j
        int p = k >> 1, w = k & 1;       // pair, half
        float* dst0 = (float*)s_pw0; dst0[(p * 8 + j) * 2 + w] = W_hh0[k * 8 + j];
        float* dst1 = (float*)s_pu1; dst1[(p * 8 + j) * 2 + w] = W_ih1[k * 8 + j];
        float* dst2 = (float*)s_pv1; dst2[(p * 8 + j) * 2 + w] = W_hh1[k * 8 + j];
    }
    if (tid < 8)  s_wlin[tid] = W_lin[tid];
    if (tid == 0) s_blin = b_lin[0];
    __syncthreads();

    int b = blockIdx.x * blockDim.x + tid;
    if (b >= Bn) return;

    float c1[8], c2[8];
    u64 hp1[8], hp2[8];   // {h, h} broadcast packs
    u64 zero = pack2(0.f, 0.f);
#pragma unroll
    for (int u = 0; u < 8; ++u) { c1[u] = 0.f; c2[u] = 0.f; hp1[u] = zero; hp2[u] = zero; }

    const u64* pb0   = (const u64*)s_pb0;
    const u64* pb1   = (const u64*)s_pb1;
    const u64* pwih0 = (const u64*)s_pwih0;

    for (int t = 0; t < T_STEPS; ++t) {
        float x = g_XT[(size_t)t * Bn + b];
        u64 xx = pack2(x, x);
        u64 acc[16];

        // ---------- layer 1 gates ----------
#pragma unroll
        for (int p = 0; p < 16; ++p) {
            u64 a = fma2(pwih0[p], xx, pb0[p]);
            const ulonglong2* row = (const ulonglong2*)&s_pw0[p][0];
#pragma unroll
            for (int q = 0; q < 4; ++q) {
                ulonglong2 wv = row[q];
                a = fma2(wv.x, hp1[2 * q], a);
                a = fma2(wv.y, hp1[2 * q + 1], a);
            }
            acc[p] = a;
        }
        {
            float g[32];
#pragma unroll
            for (int p = 0; p < 16; ++p) unpack2(acc[p], g[2 * p], g[2 * p + 1]);
#pragma unroll
            for (int u = 0; u < 8; ++u) {
                float ig = sig_hw(g[u]);
                float fg = sig_hw(g[u + 8]);
                float gg = tanhf_hw(g[u + 16]);
                float og = sig_hw(g[u + 24]);
                c1[u] = fmaf(fg, c1[u], ig * gg);
                float h = og * tanhf_hw(c1[u]);
                hp1[u] = pack2(h, h);
            }
        }

        // ---------- layer 2 gates ----------
#pragma unroll
        for (int p = 0; p < 16; ++p) {
            u64 a = pb1[p];
            const ulonglong2* rowu = (const ulonglong2*)&s_pu1[p][0];
            const ulonglong2* rowv = (const ulonglong2*)&s_pv1[p][0];
#pragma unroll
            for (int q = 0; q < 4; ++q) {
                ulonglong2 uv = rowu[q];
                a = fma2(uv.x, hp1[2 * q], a);
                a = fma2(uv.y, hp1[2 * q + 1], a);
            }
#pragma unroll
            for (int q = 0; q < 4; ++q) {
                ulonglong2 vv = rowv[q];
                a = fma2(vv.x, hp2[2 * q], a);
                a = fma2(vv.y, hp2[2 * q + 1], a);
            }
            acc[p] = a;
        }
        {
            float g[32];
#pragma unroll
            for (int p = 0; p < 16; ++p) unpack2(acc[p], g[2 * p], g[2 * p + 1]);
#pragma unroll
            for (int u = 0; u < 8; ++u) {
                float ig = sig_hw(g[u]);
                float fg = sig_hw(g[u + 8]);
                float gg = tanhf_hw(g[u + 16]);
                float og = sig_hw(g[u + 24]);
                c2[u] = fmaf(fg, c2[u], ig * gg);
                float h = og * tanhf_hw(c2[u]);
                hp2[u] = pack2(h, h);
            }
        }
    }

    // ---------- relu -> linear -> relu ----------
    float acc = s_blin;
#pragma unroll
    for (int u = 0; u < 8; ++u) {
        float h, dummy;
        unpack2(hp2[u], h, dummy);
        acc = fmaf(s_wlin[u], fmaxf(h, 0.0f), acc);
    }
    out[b] = fmaxf(acc, 0.0f);
}

extern "C" void kernel_launch(void* const* d_in, const int* in_sizes, int n_in,
                              void* d_out, int out_size) {
    const float* X     = (const float*)d_in[0];
    const float* W_ih0 = (const float*)d_in[1];
    const float* W_hh0 = (const float*)d_in[2];
    const float* b_ih0 = (const float*)d_in[3];
    const float* b_hh0 = (const float*)d_in[4];
    const float* W_ih1 = (const float*)d_in[5];
    const float* W_hh1 = (const float*)d_in[6];
    const float* b_ih1 = (const float*)d_in[7];
    const float* b_hh1 = (const float*)d_in[8];
    const float* W_lin = (const float*)d_in[9];
    const float* b_lin = (const float*)d_in[10];

    int Bn = out_size;
    transpose_x_kernel<<<(Bn + 31) / 32, 256>>>(X, Bn);
    lstm_fused_kernel<<<(Bn + 255) / 256, 256>>>(
        W_ih0, W_hh0, b_ih0, b_hh0,
        W_ih1, W_hh1, b_ih1, b_hh1,
        W_lin, b_lin, (float*)d_out, Bn);
}